// round 14
// baseline (speedup 1.0000x reference)
#include <cuda_runtime.h>
#include <math_constants.h>

#define NTRK 4096
#define NB 64
#define NBINS (NB * NB)
#define FULLMASK 0xffffffffu
#define THREADS 1024
#define TRACKS_PER_BLOCK 32

// fixed bbox (exact for any input via clamping; bound argument below)
#define BB_MIN (-6.0f)
#define BB_W   (12.0f)
#define CW     (BB_W / (float)NB)    // 0.1875, exact in fp32
#define INVW   ((float)NB / BB_W)
#define EPSB   0.0005f               // fp safety margin

// smem layout
#define SM_PTS_OFF  0                // float4[4096] = 65536
#define SM_OFS_OFF  65536            // int[4097]    = 16388
#define SM_WSUM_OFF (65536 + 16400)  // int[32]      = 128
#define SM_TOTAL    (65536 + 16400 + 128)

// lexicographic (d2, idx) insert into a sorted-4 list; exact top_k tie-break.
// Order-independent, so any scan order is exact.
__device__ __forceinline__ void lex_insert(float dv, int jv,
    float& s0, float& s1, float& s2, float& s3,
    int& i0, int& i1, int& i2, int& i3)
{
    bool l3 = (dv < s3) || (dv == s3 && jv < i3);
    if (l3) {
        bool l1 = (dv < s1) || (dv == s1 && jv < i1);
        if (l1) {
            s3 = s2; i3 = i2; s2 = s1; i2 = i1;
            bool l0 = (dv < s0) || (dv == s0 && jv < i0);
            if (l0) { s1 = s0; i1 = i0; s0 = dv; i0 = jv; }
            else    { s1 = dv; i1 = jv; }
        } else {
            bool l2 = (dv < s2) || (dv == s2 && jv < i2);
            if (l2) { s3 = s2; i3 = i2; s2 = dv; i2 = jv; }
            else    { s3 = dv; i3 = jv; }
        }
    }
}

__global__ __launch_bounds__(THREADS)
void nn_pool_fused(const float2* __restrict__ obs1,
                   const float2* __restrict__ obs2,
                   const float* __restrict__ W,
                   const float* __restrict__ bias,
                   float* __restrict__ out,
                   int n)
{
    extern __shared__ char smem_raw[];
    float4* s_pts  = (float4*)(smem_raw + SM_PTS_OFF);
    int*    s_ofs  = (int*)   (smem_raw + SM_OFS_OFF);   // [NBINS+1]
    int*    s_wsum = (int*)   (smem_raw + SM_WSUM_OFF);

    const int t    = threadIdx.x;
    const int lane = t & 31;
    const int warp = t >> 5;

    // ---------------- per-block grid build (all in SMEM) ----------------
    for (int c = t; c < NBINS + 1; c += THREADS) s_ofs[c] = 0;
    __syncthreads();

    float px[4], py[4];
    int   bins[4], rank[4];
    #pragma unroll
    for (int k = 0; k < 4; ++k) {
        int p = t + k * THREADS;
        bins[k] = -1;
        if (p < n) {
            float2 v = obs2[p];
            px[k] = v.x; py[k] = v.y;
            int bx = min(NB - 1, max(0, (int)((v.x - BB_MIN) * INVW)));
            int by = min(NB - 1, max(0, (int)((v.y - BB_MIN) * INVW)));
            bins[k] = by * NB + bx;
            rank[k] = atomicAdd(&s_ofs[bins[k]], 1);  // return value = rank
        }
    }
    __syncthreads();

    int c4[4];
    #pragma unroll
    for (int k = 0; k < 4; ++k) c4[k] = s_ofs[4 * t + k];
    int tot = c4[0] + c4[1] + c4[2] + c4[3];
    int incl = tot;
    #pragma unroll
    for (int off = 1; off < 32; off <<= 1) {
        int v = __shfl_up_sync(FULLMASK, incl, off);
        if (lane >= off) incl += v;
    }
    if (lane == 31) s_wsum[warp] = incl;
    __syncthreads();
    if (warp == 0) {
        int v = s_wsum[lane];
        int wi = v;
        #pragma unroll
        for (int off = 1; off < 32; off <<= 1) {
            int u = __shfl_up_sync(FULLMASK, wi, off);
            if (lane >= off) wi += u;
        }
        s_wsum[lane] = wi - v;
    }
    __syncthreads();
    int run = s_wsum[warp] + (incl - tot);
    #pragma unroll
    for (int k = 0; k < 4; ++k) {
        s_ofs[4 * t + k] = run;
        run += c4[k];
    }
    if (t == THREADS - 1) s_ofs[NBINS] = run;
    __syncthreads();

    #pragma unroll
    for (int k = 0; k < 4; ++k) {
        if (bins[k] >= 0) {
            s_pts[s_ofs[bins[k]] + rank[k]] =
                make_float4(px[k], py[k], __int_as_float(t + k * THREADS), 0.0f);
        }
    }
    __syncthreads();

    // ---------------- search: one warp per track, all SMEM ----------------
    const int i = blockIdx.x * TRACKS_PER_BLOCK + warp;
    if (i >= n) return;

    const float2 q = obs2[i];
    const float qx = q.x, qy = q.y;

    const int cx = min(NB - 1, max(0, (int)((qx - BB_MIN) * INVW)));
    const int cy = min(NB - 1, max(0, (int)((qy - BB_MIN) * INVW)));

    float s0 = CUDART_INF_F, s1 = CUDART_INF_F, s2 = CUDART_INF_F, s3 = CUDART_INF_F;
    int   i0 = n, i1 = n, i2 = n, i3 = n;

    // warp-cooperative span scan: all 32 lanes stride one contiguous span
    #define SPAN_SCAN(bg_, en_)                                        \
        for (int p = (bg_) + lane; p < (en_); p += 32) {               \
            float4 pt = s_pts[p];                                      \
            int pj = __float_as_int(pt.z);                             \
            float dx = pt.x - qx, dy = pt.y - qy;                      \
            float dd = fmaf(dx, dx, dy * dy);                          \
            if (pj != i) lex_insert(dd, pj, s0, s1, s2, s3, i0, i1, i2, i3); \
        }

    // initial 3x3 rect: rows sequential, spans warp-cooperative
    int x0 = max(cx - 1, 0), x1 = min(cx + 1, NB - 1);
    int y0 = max(cy - 1, 0), y1 = min(cy + 1, NB - 1);
    for (int y = y0; y <= y1; ++y) {
        int r = y * NB;
        int bg = s_ofs[r + x0], en = s_ofs[r + x1 + 1];
        SPAN_SCAN(bg, en);
    }

    while (true) {
        // lower bound on distance to any unprocessed point. Grid-edge sides
        // contribute +inf: all points (incl. clamped outliers) live in bins
        // 0..NB-1, and a clamped outlier lies farther out than its bin's
        // nominal region, so interior-side bounds remain valid lower bounds.
        float bl = (x0 > 0)      ? (qx - (BB_MIN + (float)x0 * CW))       : CUDART_INF_F;
        float br = (x1 < NB - 1) ? ((BB_MIN + (float)(x1 + 1) * CW) - qx) : CUDART_INF_F;
        float bd = (y0 > 0)      ? (qy - (BB_MIN + (float)y0 * CW))       : CUDART_INF_F;
        float bu = (y1 < NB - 1) ? ((BB_MIN + (float)(y1 + 1) * CW) - qy) : CUDART_INF_F;
        float bmin = fminf(fminf(bl, br), fminf(bd, bu));

        if (isinf(bmin)) break;   // rect covers entire grid

        float be = fmaxf(bmin - EPSB, 0.0f);
        float b2 = be * be;
        // exact termination: lane lists hold DISJOINT candidates, so
        // sum(cnt) >= 4  <=>  >=4 distinct points with d2 <= b2, all strictly
        // nearer than any unprocessed point.
        int cnt = (s3 <= b2) ? 4 : (s2 <= b2) ? 3 : (s1 <= b2) ? 2 : (s0 <= b2) ? 1 : 0;
        if (__reduce_add_sync(FULLMASK, cnt) >= 4) break;

        // not done: compute EXACT warp-global 4th-best (lex) by merging lane
        // lists into temporaries (lane lists untouched -> remain disjoint)
        float c0 = s0, c1 = s1, c2 = s2, c3 = s3;
        int   d0 = i0, d1 = i1, d2 = i2, d3 = i3;
        #pragma unroll
        for (int off = 16; off > 0; off >>= 1) {
            float m0 = __shfl_xor_sync(FULLMASK, c0, off);
            float m1 = __shfl_xor_sync(FULLMASK, c1, off);
            float m2 = __shfl_xor_sync(FULLMASK, c2, off);
            float m3 = __shfl_xor_sync(FULLMASK, c3, off);
            int   e0 = __shfl_xor_sync(FULLMASK, d0, off);
            int   e1 = __shfl_xor_sync(FULLMASK, d1, off);
            int   e2 = __shfl_xor_sync(FULLMASK, d2, off);
            int   e3 = __shfl_xor_sync(FULLMASK, d3, off);
            lex_insert(m0, e0, c0, c1, c2, c3, d0, d1, d2, d3);
            lex_insert(m1, e1, c0, c1, c2, c3, d0, d1, d2, d3);
            lex_insert(m2, e2, c0, c1, c2, c3, d0, d1, d2, d3);
            lex_insert(m3, e3, c0, c1, c2, c3, d0, d1, d2, d3);
        }
        // c3 = exact global 4th-best d2 over processed points (inf if <4 seen)

        int nx0, nx1, ny0, ny1;
        if (c3 < CUDART_INF_F) {
            // tight jump: the true 4 nearest lie within radius sqrt(c3)+eps
            float ru = sqrtf(c3) + EPSB;
            nx0 = min(x0, max(0,      (int)((qx - ru - BB_MIN) * INVW)));
            nx1 = max(x1, min(NB - 1, (int)((qx + ru - BB_MIN) * INVW)));
            ny0 = min(y0, max(0,      (int)((qy - ru - BB_MIN) * INVW)));
            ny1 = max(y1, min(NB - 1, (int)((qy + ru - BB_MIN) * INVW)));
            if (nx0 == x0 && nx1 == x1 && ny0 == y0 && ny1 == y1) {
                // fp edge: force progress
                nx0 = max(x0 - 1, 0); nx1 = min(x1 + 1, NB - 1);
                ny0 = max(y0 - 1, 0); ny1 = min(y1 + 1, NB - 1);
            }
        } else {
            // warp has <4 candidates total: stride 2 across sparse space
            nx0 = max(x0 - 2, 0); nx1 = min(x1 + 2, NB - 1);
            ny0 = max(y0 - 2, 0); ny1 = min(y1 + 2, NB - 1);
        }

        // delta scan: rows sequential (warp-uniform), spans warp-cooperative
        for (int yy = ny0; yy <= ny1; ++yy) {
            int r = yy * NB;
            if (yy < y0 || yy > y1) {
                int bg = s_ofs[r + nx0], en = s_ofs[r + nx1 + 1];
                SPAN_SCAN(bg, en);
            } else {
                if (nx0 < x0) {
                    int bg = s_ofs[r + nx0], en = s_ofs[r + x0];
                    SPAN_SCAN(bg, en);
                }
                if (nx1 > x1) {
                    int bg = s_ofs[r + x1 + 1], en = s_ofs[r + nx1 + 1];
                    SPAN_SCAN(bg, en);
                }
            }
        }
        x0 = nx0; x1 = nx1; y0 = ny0; y1 = ny1;
    }

    // final butterfly merge: lane lists are disjoint, so merging them yields
    // the exact global lex top-4 in every lane
    #pragma unroll
    for (int off = 16; off > 0; off >>= 1) {
        float m0 = __shfl_xor_sync(FULLMASK, s0, off);
        float m1 = __shfl_xor_sync(FULLMASK, s1, off);
        float m2 = __shfl_xor_sync(FULLMASK, s2, off);
        float m3 = __shfl_xor_sync(FULLMASK, s3, off);
        int   e0 = __shfl_xor_sync(FULLMASK, i0, off);
        int   e1 = __shfl_xor_sync(FULLMASK, i1, off);
        int   e2 = __shfl_xor_sync(FULLMASK, i2, off);
        int   e3 = __shfl_xor_sync(FULLMASK, i3, off);
        lex_insert(m0, e0, s0, s1, s2, s3, i0, i1, i2, i3);
        lex_insert(m1, e1, s0, s1, s2, s3, i0, i1, i2, i3);
        lex_insert(m2, e2, s0, s1, s2, s3, i0, i1, i2, i3);
        lex_insert(m3, e3, s0, s1, s2, s3, i0, i1, i2, i3);
    }

    // epilogue: lane = k*8 + e computes out[i][k*8 + e]
    const int k = lane >> 3;
    const int e = lane & 7;
    int nj = (k == 0) ? i0 : (k == 1) ? i1 : (k == 2) ? i2 : i3;
    if (nj >= n) nj = (i == 0) ? 1 : 0;   // degenerate-n safety

    float2 pj  = obs2[nj];
    float2 o1j = obs1[nj];
    float2 o1i = obs1[i];

    float rpx = pj.x - qx;
    float rpy = pj.y - qy;
    float rvx = (pj.x - o1j.x) - (qx - o1i.x);
    float rvy = (pj.y - o1j.y) - (qy - o1i.y);

    float acc = bias[e];
    acc = fmaf(rpx, W[0 * 8 + e], acc);
    acc = fmaf(rpy, W[1 * 8 + e], acc);
    acc = fmaf(rvx, W[2 * 8 + e], acc);
    acc = fmaf(rvy, W[3 * 8 + e], acc);

    out[i * 32 + lane] = fmaxf(acc, 0.0f);
}

extern "C" void kernel_launch(void* const* d_in, const int* in_sizes, int n_in,
                              void* d_out, int out_size) {
    const float2* obs1 = (const float2*)d_in[0];  // [N, 2]
    const float2* obs2 = (const float2*)d_in[1];  // [N, 2]
    const float*  W    = (const float*)d_in[2];   // [4, 8]
    const float*  b    = (const float*)d_in[3];   // [8]
    float* out = (float*)d_out;                    // [N, 32]

    int n = in_sizes[0] / 2;
    if (n > NTRK) n = NTRK;

    static bool attr_set = false;
    if (!attr_set) {
        cudaFuncSetAttribute(nn_pool_fused,
                             cudaFuncAttributeMaxDynamicSharedMemorySize,
                             SM_TOTAL);
        attr_set = true;
    }

    int blocks = (n + TRACKS_PER_BLOCK - 1) / TRACKS_PER_BLOCK;
    nn_pool_fused<<<blocks, THREADS, SM_TOTAL>>>(obs1, obs2, W, b, out, n);
}

// round 15
// speedup vs baseline: 1.1412x; 1.1412x over previous
#include <cuda_runtime.h>
#include <math_constants.h>

#define NTRK 4096
#define NB 64
#define NBINS (NB * NB)
#define FULLMASK 0xffffffffu
#define THREADS 1024
#define TRACKS_PER_BLOCK 32

// fixed bbox (exact for any input via clamping; bound argument below)
#define BB_MIN (-6.0f)
#define BB_W   (12.0f)
#define CW     (BB_W / (float)NB)    // 0.1875, exact in fp32
#define INVW   ((float)NB / BB_W)
#define EPSB   0.0005f               // fp safety margin

// smem layout
#define SM_PTS_OFF  0                // float4[4096] = 65536
#define SM_OFS_OFF  65536            // int[4097]    = 16388
#define SM_WSUM_OFF (65536 + 16400)  // int[32]      = 128
#define SM_TOTAL    (65536 + 16400 + 128)

#define INF CUDART_INF_F

// lexicographic (d2, idx) insert into a sorted-4 list; exact top_k tie-break.
__device__ __forceinline__ void lex_insert(float dv, int jv,
    float& s0, float& s1, float& s2, float& s3,
    int& i0, int& i1, int& i2, int& i3)
{
    if ((dv < s3) || (dv == s3 && jv < i3)) {
        if ((dv < s1) || (dv == s1 && jv < i1)) {
            s3 = s2; i3 = i2; s2 = s1; i2 = i1;
            if ((dv < s0) || (dv == s0 && jv < i0)) { s1 = s0; i1 = i0; s0 = dv; i0 = jv; }
            else                                    { s1 = dv; i1 = jv; }
        } else {
            if ((dv < s2) || (dv == s2 && jv < i2)) { s3 = s2; i3 = i2; s2 = dv; i2 = jv; }
            else                                    { s3 = dv; i3 = jv; }
        }
    }
}

__global__ __launch_bounds__(THREADS)
void nn_pool_fused(const float2* __restrict__ obs1,
                   const float2* __restrict__ obs2,
                   const float* __restrict__ W,
                   const float* __restrict__ bias,
                   float* __restrict__ out,
                   int n)
{
    extern __shared__ char smem_raw[];
    float4* s_pts  = (float4*)(smem_raw + SM_PTS_OFF);
    int*    s_ofs  = (int*)   (smem_raw + SM_OFS_OFF);   // [NBINS+1]
    int*    s_wsum = (int*)   (smem_raw + SM_WSUM_OFF);

    const int t    = threadIdx.x;
    const int lane = t & 31;
    const int warp = t >> 5;

    // ---------------- per-block grid build (all in SMEM, as R11) -----------
    for (int c = t; c < NBINS + 1; c += THREADS) s_ofs[c] = 0;
    __syncthreads();

    float px[4], py[4];
    int   bins[4], rank[4];
    #pragma unroll
    for (int k = 0; k < 4; ++k) {
        int p = t + k * THREADS;
        bins[k] = -1;
        if (p < n) {
            float2 v = obs2[p];
            px[k] = v.x; py[k] = v.y;
            int bx = min(NB - 1, max(0, (int)((v.x - BB_MIN) * INVW)));
            int by = min(NB - 1, max(0, (int)((v.y - BB_MIN) * INVW)));
            bins[k] = by * NB + bx;
            rank[k] = atomicAdd(&s_ofs[bins[k]], 1);  // return value = rank
        }
    }
    __syncthreads();

    int c4[4];
    #pragma unroll
    for (int k = 0; k < 4; ++k) c4[k] = s_ofs[4 * t + k];
    int tot = c4[0] + c4[1] + c4[2] + c4[3];
    int incl = tot;
    #pragma unroll
    for (int off = 1; off < 32; off <<= 1) {
        int v = __shfl_up_sync(FULLMASK, incl, off);
        if (lane >= off) incl += v;
    }
    if (lane == 31) s_wsum[warp] = incl;
    __syncthreads();
    if (warp == 0) {
        int v = s_wsum[lane];
        int wi = v;
        #pragma unroll
        for (int off = 1; off < 32; off <<= 1) {
            int u = __shfl_up_sync(FULLMASK, wi, off);
            if (lane >= off) wi += u;
        }
        s_wsum[lane] = wi - v;
    }
    __syncthreads();
    int run = s_wsum[warp] + (incl - tot);
    #pragma unroll
    for (int k = 0; k < 4; ++k) {
        s_ofs[4 * t + k] = run;
        run += c4[k];
    }
    if (t == THREADS - 1) s_ofs[NBINS] = run;
    __syncthreads();

    #pragma unroll
    for (int k = 0; k < 4; ++k) {
        if (bins[k] >= 0) {
            s_pts[s_ofs[bins[k]] + rank[k]] =
                make_float4(px[k], py[k], __int_as_float(t + k * THREADS), 0.0f);
        }
    }
    __syncthreads();

    // ---------------- search: one warp per track, all SMEM ----------------
    const int i = blockIdx.x * TRACKS_PER_BLOCK + warp;
    if (i >= n) return;

    const float2 q = obs2[i];
    const float qx = q.x, qy = q.y;

    const int cx = min(NB - 1, max(0, (int)((qx - BB_MIN) * INVW)));
    const int cy = min(NB - 1, max(0, (int)((qy - BB_MIN) * INVW)));

    float s0 = INF, s1 = INF, s2 = INF, s3 = INF;
    int   i0 = n,  i1 = n,  i2 = n,  i3 = n;

    #define PROC1(p_)                                                  \
        do {                                                           \
            float4 pt = s_pts[p_];                                     \
            int pj = __float_as_int(pt.z);                             \
            float dx = pt.x - qx, dy = pt.y - qy;                      \
            float dd = fmaf(dx, dx, dy * dy);                          \
            if (pj != i) lex_insert(dd, pj, s0, s1, s2, s3, i0, i1, i2, i3); \
        } while (0)

    // warp-cooperative span scan (lane-striped: disjoint partition of indices)
    #define SPAN_SCAN(bg_, en_)                                        \
        for (int p = (bg_) + lane; p < (en_); p += 32) PROC1(p);

    // ---- Phase 1: home cell only ----
    int x0 = cx, x1 = cx, y0 = cy, y1 = cy;
    {
        int r = cy * NB;
        int bg = s_ofs[r + cx], en = s_ofs[r + cx + 1];
        SPAN_SCAN(bg, en);
    }
    int mycnt = (s0 < INF) + (s1 < INF) + (s2 < INF) + (s3 < INF);
    int total = __reduce_add_sync(FULLMASK, mycnt);

    // ---- Phase 2 (rare): expand by 2 lane-per-row until >=4 candidates ----
    while (total < 4 && !(x0 == 0 && x1 == NB - 1 && y0 == 0 && y1 == NB - 1)) {
        int nx0 = max(x0 - 2, 0), nx1 = min(x1 + 2, NB - 1);
        int ny0 = max(y0 - 2, 0), ny1 = min(y1 + 2, NB - 1);
        for (int yy = ny0 + lane; yy <= ny1; yy += 32) {
            int rr = yy * NB;
            if (yy < y0 || yy > y1) {
                int bg = s_ofs[rr + nx0], en = s_ofs[rr + nx1 + 1];
                for (int p = bg; p < en; ++p) PROC1(p);
            } else {
                if (nx0 < x0) {
                    int bg = s_ofs[rr + nx0], en = s_ofs[rr + x0];
                    for (int p = bg; p < en; ++p) PROC1(p);
                }
                if (nx1 > x1) {
                    int bg = s_ofs[rr + x1 + 1], en = s_ofs[rr + nx1 + 1];
                    for (int p = bg; p < en; ++p) PROC1(p);
                }
            }
        }
        x0 = nx0; x1 = nx1; y0 = ny0; y1 = ny1;
        mycnt = (s0 < INF) + (s1 < INF) + (s2 < INF) + (s3 < INF);
        total = __reduce_add_sync(FULLMASK, mycnt);
    }

    // ---- Phase 3: extract EXACT top-4-so-far into warp-replicated g via
    // REDUX pop rounds. Lane lists hold disjoint points (unique idx), so each
    // pop removes exactly one point; extracted 4 strictly dominate all
    // remaining seen points -> lane lists can be reset afterwards.
    float gd0, gd1, gd2, gd3;
    int   gi0, gi1, gi2, gi3;
    #define POP_ROUND(GD, GI)                                              \
        do {                                                               \
            unsigned um = __reduce_min_sync(FULLMASK, __float_as_uint(s0));\
            int cand = (__float_as_uint(s0) == um) ? i0 : 0x7FFFFFFF;      \
            int im = __reduce_min_sync(FULLMASK, cand);                    \
            if (__float_as_uint(s0) == um && i0 == im) {                   \
                s0 = s1; i0 = i1; s1 = s2; i1 = i2;                        \
                s2 = s3; i2 = i3; s3 = INF; i3 = n;                        \
            }                                                              \
            GD = __uint_as_float(um); GI = im;                             \
        } while (0)
    POP_ROUND(gd0, gi0);
    POP_ROUND(gd1, gi1);
    POP_ROUND(gd2, gi2);
    POP_ROUND(gd3, gi3);
    s0 = s1 = s2 = s3 = INF;
    i0 = i1 = i2 = i3 = n;

    // ---- Phase 4: ONE jump — scan delta of rect covering disc(sqrt(gd3)+eps).
    // All points within the true 4th-NN disc (subset of this disc) get
    // examined -> after this the warp has seen every top-4 candidate.
    // Grid-edge clamping stays exact: outliers live in edge bins, and the
    // disc reaching past the data region forces the rect to the edge bins.
    if (gd3 < INF) {
        float ru = sqrtf(gd3) + EPSB;
        int jx0 = max(0,      (int)((qx - ru - BB_MIN) * INVW));
        int jx1 = min(NB - 1, (int)((qx + ru - BB_MIN) * INVW));
        int jy0 = max(0,      (int)((qy - ru - BB_MIN) * INVW));
        int jy1 = min(NB - 1, (int)((qy + ru - BB_MIN) * INVW));
        int nx0 = min(x0, jx0), nx1 = max(x1, jx1);
        int ny0 = min(y0, jy0), ny1 = max(y1, jy1);
        for (int yy = ny0; yy <= ny1; ++yy) {
            int rr = yy * NB;
            if (yy < y0 || yy > y1) {
                int bg = s_ofs[rr + nx0], en = s_ofs[rr + nx1 + 1];
                SPAN_SCAN(bg, en);
            } else {
                if (nx0 < x0) {
                    int bg = s_ofs[rr + nx0], en = s_ofs[rr + x0];
                    SPAN_SCAN(bg, en);
                }
                if (nx1 > x1) {
                    int bg = s_ofs[rr + x1 + 1], en = s_ofs[rr + nx1 + 1];
                    SPAN_SCAN(bg, en);
                }
            }
        }
    }

    // ---- Phase 5: final exact top-4 = 4 pop rounds over (replicated g-list
    // + disjoint lane lists). g and delta points are disjoint (delta cells
    // exclude the old window). Results replicated in all lanes.
    int gp = 0;
    int nn0, nn1, nn2, nn3;
    #define FIN_ROUND(NN)                                                  \
        do {                                                               \
            float gh  = (gp == 0) ? gd0 : (gp == 1) ? gd1 :                \
                        (gp == 2) ? gd2 : (gp == 3) ? gd3 : INF;           \
            int   ghi = (gp == 0) ? gi0 : (gp == 1) ? gi1 :                \
                        (gp == 2) ? gi2 : (gp == 3) ? gi3 : n;             \
            float hd; int hi;                                              \
            if ((gh < s0) || (gh == s0 && ghi < i0)) { hd = gh; hi = ghi; }\
            else                                     { hd = s0; hi = i0; } \
            unsigned um = __reduce_min_sync(FULLMASK, __float_as_uint(hd));\
            int cand = (__float_as_uint(hd) == um) ? hi : 0x7FFFFFFF;      \
            int im = __reduce_min_sync(FULLMASK, cand);                    \
            if (__float_as_uint(gh) == um && ghi == im) {                  \
                gp++;                           /* uniform: g replicated */\
            } else if (__float_as_uint(s0) == um && i0 == im) {            \
                s0 = s1; i0 = i1; s1 = s2; i1 = i2;                        \
                s2 = s3; i2 = i3; s3 = INF; i3 = n;                        \
            }                                                              \
            NN = im;                                                       \
        } while (0)
    FIN_ROUND(nn0);
    FIN_ROUND(nn1);
    FIN_ROUND(nn2);
    FIN_ROUND(nn3);

    // epilogue: lane = k*8 + e computes out[i][k*8 + e]
    const int k = lane >> 3;
    const int e = lane & 7;
    int nj = (k == 0) ? nn0 : (k == 1) ? nn1 : (k == 2) ? nn2 : nn3;
    if (nj >= n) nj = (i == 0) ? 1 : 0;   // degenerate-n safety

    float2 pj  = obs2[nj];
    float2 o1j = obs1[nj];
    float2 o1i = obs1[i];

    float rpx = pj.x - qx;
    float rpy = pj.y - qy;
    float rvx = (pj.x - o1j.x) - (qx - o1i.x);
    float rvy = (pj.y - o1j.y) - (qy - o1i.y);

    float acc = bias[e];
    acc = fmaf(rpx, W[0 * 8 + e], acc);
    acc = fmaf(rpy, W[1 * 8 + e], acc);
    acc = fmaf(rvx, W[2 * 8 + e], acc);
    acc = fmaf(rvy, W[3 * 8 + e], acc);

    out[i * 32 + lane] = fmaxf(acc, 0.0f);
}

extern "C" void kernel_launch(void* const* d_in, const int* in_sizes, int n_in,
                              void* d_out, int out_size) {
    const float2* obs1 = (const float2*)d_in[0];  // [N, 2]
    const float2* obs2 = (const float2*)d_in[1];  // [N, 2]
    const float*  W    = (const float*)d_in[2];   // [4, 8]
    const float*  b    = (const float*)d_in[3];   // [8]
    float* out = (float*)d_out;                    // [N, 32]

    int n = in_sizes[0] / 2;
    if (n > NTRK) n = NTRK;

    static bool attr_set = false;
    if (!attr_set) {
        cudaFuncSetAttribute(nn_pool_fused,
                             cudaFuncAttributeMaxDynamicSharedMemorySize,
                             SM_TOTAL);
        attr_set = true;
    }

    int blocks = (n + TRACKS_PER_BLOCK - 1) / TRACKS_PER_BLOCK;
    nn_pool_fused<<<blocks, THREADS, SM_TOTAL>>>(obs1, obs2, W, b, out, n);
}

// round 16
// speedup vs baseline: 1.6610x; 1.4555x over previous
#include <cuda_runtime.h>
#include <math_constants.h>

#define NTRK 4096
#define NB 64
#define NBINS (NB * NB)
#define FULLMASK 0xffffffffu
#define THREADS 1024
#define TRACKS_PER_BLOCK 28          // 147 blocks -> all 148 SMs busy

// fixed bbox (exact for any input via clamping; bound argument below)
#define BB_MIN (-6.0f)
#define BB_W   (12.0f)
#define CW     (BB_W / (float)NB)    // 0.1875, exact in fp32
#define INVW   ((float)NB / BB_W)
#define EPSB   0.0005f               // fp safety margin

// smem layout
#define SM_PTS_OFF  0                // float4[4096] = 65536
#define SM_OFS_OFF  65536            // int[4097]    = 16388
#define SM_WSUM_OFF (65536 + 16400)  // int[32]      = 128
#define SM_TOTAL    (65536 + 16400 + 128)

#define INF CUDART_INF_F

// lexicographic (d2, idx) insert into a sorted-4 list; exact top_k tie-break.
// Order-independent, so any scan order is exact.
__device__ __forceinline__ void lex_insert(float dv, int jv,
    float& s0, float& s1, float& s2, float& s3,
    int& i0, int& i1, int& i2, int& i3)
{
    if ((dv < s3) || (dv == s3 && jv < i3)) {
        if ((dv < s1) || (dv == s1 && jv < i1)) {
            s3 = s2; i3 = i2; s2 = s1; i2 = i1;
            if ((dv < s0) || (dv == s0 && jv < i0)) { s1 = s0; i1 = i0; s0 = dv; i0 = jv; }
            else                                    { s1 = dv; i1 = jv; }
        } else {
            if ((dv < s2) || (dv == s2 && jv < i2)) { s3 = s2; i3 = i2; s2 = dv; i2 = jv; }
            else                                    { s3 = dv; i3 = jv; }
        }
    }
}

__global__ __launch_bounds__(THREADS)
void nn_pool_fused(const float2* __restrict__ obs1,
                   const float2* __restrict__ obs2,
                   const float* __restrict__ W,
                   const float* __restrict__ bias,
                   float* __restrict__ out,
                   int n)
{
    extern __shared__ char smem_raw[];
    float4* s_pts  = (float4*)(smem_raw + SM_PTS_OFF);
    int*    s_ofs  = (int*)   (smem_raw + SM_OFS_OFF);   // [NBINS+1]
    int*    s_wsum = (int*)   (smem_raw + SM_WSUM_OFF);

    const int t    = threadIdx.x;
    const int lane = t & 31;
    const int warp = t >> 5;

    // ---------------- per-block grid build (all in SMEM, R11-proven) -------
    for (int c = t; c < NBINS + 1; c += THREADS) s_ofs[c] = 0;
    __syncthreads();

    float px[4], py[4];
    int   bins[4], rank[4];
    #pragma unroll
    for (int k = 0; k < 4; ++k) {
        int p = t + k * THREADS;
        bins[k] = -1;
        if (p < n) {
            float2 v = obs2[p];
            px[k] = v.x; py[k] = v.y;
            int bx = min(NB - 1, max(0, (int)((v.x - BB_MIN) * INVW)));
            int by = min(NB - 1, max(0, (int)((v.y - BB_MIN) * INVW)));
            bins[k] = by * NB + bx;
            rank[k] = atomicAdd(&s_ofs[bins[k]], 1);  // return value = rank
        }
    }
    __syncthreads();

    int c4[4];
    #pragma unroll
    for (int k = 0; k < 4; ++k) c4[k] = s_ofs[4 * t + k];
    int tot = c4[0] + c4[1] + c4[2] + c4[3];
    int incl = tot;
    #pragma unroll
    for (int off = 1; off < 32; off <<= 1) {
        int v = __shfl_up_sync(FULLMASK, incl, off);
        if (lane >= off) incl += v;
    }
    if (lane == 31) s_wsum[warp] = incl;
    __syncthreads();
    if (warp == 0) {
        int v = s_wsum[lane];
        int wi = v;
        #pragma unroll
        for (int off = 1; off < 32; off <<= 1) {
            int u = __shfl_up_sync(FULLMASK, wi, off);
            if (lane >= off) wi += u;
        }
        s_wsum[lane] = wi - v;
    }
    __syncthreads();
    int run = s_wsum[warp] + (incl - tot);
    #pragma unroll
    for (int k = 0; k < 4; ++k) {
        s_ofs[4 * t + k] = run;
        run += c4[k];
    }
    if (t == THREADS - 1) s_ofs[NBINS] = run;
    __syncthreads();

    #pragma unroll
    for (int k = 0; k < 4; ++k) {
        if (bins[k] >= 0) {
            s_pts[s_ofs[bins[k]] + rank[k]] =
                make_float4(px[k], py[k], __int_as_float(t + k * THREADS), 0.0f);
        }
    }
    __syncthreads();

    // ---------------- search: one warp per track, all SMEM ----------------
    const int i = blockIdx.x * TRACKS_PER_BLOCK + warp;
    if (warp >= TRACKS_PER_BLOCK || i >= n) return;

    const float2 q = obs2[i];
    const float qx = q.x, qy = q.y;
    const float2 o1i = obs1[i];    // prefetch: hides L2 latency behind search

    const int cx = min(NB - 1, max(0, (int)((qx - BB_MIN) * INVW)));
    const int cy = min(NB - 1, max(0, (int)((qy - BB_MIN) * INVW)));

    float s0 = INF, s1 = INF, s2 = INF, s3 = INF;
    int   i0 = n,  i1 = n,  i2 = n,  i3 = n;

    #define PROC1(p_)                                                  \
        do {                                                           \
            float4 pt = s_pts[p_];                                     \
            int pj = __float_as_int(pt.z);                             \
            float dx = pt.x - qx, dy = pt.y - qy;                      \
            float dd = fmaf(dx, dx, dy * dy);                          \
            if (pj != i) lex_insert(dd, pj, s0, s1, s2, s3, i0, i1, i2, i3); \
        } while (0)

    #define SPAN_SCAN(bg_, en_)                                        \
        for (int p = (bg_) + lane; p < (en_); p += 32) PROC1(p);

    // initial 3x3 rect: each row is a contiguous span, scanned lane-striped
    int x0 = max(cx - 1, 0), x1 = min(cx + 1, NB - 1);
    int y0 = max(cy - 1, 0), y1 = min(cy + 1, NB - 1);
    for (int y = y0; y <= y1; ++y) {
        int r = y * NB;
        int bg = s_ofs[r + x0], en = s_ofs[r + x1 + 1];
        SPAN_SCAN(bg, en);
    }

    while (true) {
        // lower bound on distance to any unprocessed point. Grid-edge sides
        // contribute +inf: all points (incl. clamped outliers) live in bins
        // 0..NB-1, and a clamped outlier lies farther out than its bin's
        // nominal region, so interior-side bounds remain valid lower bounds.
        float bl = (x0 > 0)      ? (qx - (BB_MIN + (float)x0 * CW))       : INF;
        float br = (x1 < NB - 1) ? ((BB_MIN + (float)(x1 + 1) * CW) - qx) : INF;
        float bd = (y0 > 0)      ? (qy - (BB_MIN + (float)y0 * CW))       : INF;
        float bu = (y1 < NB - 1) ? ((BB_MIN + (float)(y1 + 1) * CW) - qy) : INF;
        float bmin = fminf(fminf(bl, br), fminf(bd, bu));

        if (isinf(bmin)) break;   // rect covers entire grid

        float be = fmaxf(bmin - EPSB, 0.0f);
        float b2 = be * be;
        // exact termination: lane lists hold DISJOINT candidates, so
        // sum(cnt) >= 4 <=> >=4 distinct points strictly nearer than any
        // unprocessed point.
        int cnt = (s3 <= b2) ? 4 : (s2 <= b2) ? 3 : (s1 <= b2) ? 2 : (s0 <= b2) ? 1 : 0;
        if (__reduce_add_sync(FULLMASK, cnt) >= 4) break;

        // U = min over lanes of s3 (positive floats / +inf are int-ordered):
        // valid upper bound on global 4th-best d2 once any lane holds 4.
        float U = __uint_as_float(__reduce_min_sync(FULLMASK, __float_as_uint(s3)));

        int nx0, nx1, ny0, ny1;
        if (U < INF) {
            // jump: final answer lies within radius sqrt(U)+eps of q
            float ru = sqrtf(U) + EPSB;
            nx0 = min(x0, max(0,      (int)((qx - ru - BB_MIN) * INVW)));
            nx1 = max(x1, min(NB - 1, (int)((qx + ru - BB_MIN) * INVW)));
            ny0 = min(y0, max(0,      (int)((qy - ru - BB_MIN) * INVW)));
            ny1 = max(y1, min(NB - 1, (int)((qy + ru - BB_MIN) * INVW)));
            if (nx0 == x0 && nx1 == x1 && ny0 == y0 && ny1 == y1) {
                // fp edge: force progress
                nx0 = max(x0 - 1, 0); nx1 = min(x1 + 1, NB - 1);
                ny0 = max(y0 - 1, 0); ny1 = min(y1 + 1, NB - 1);
            }
        } else {
            // sparse neighborhood: stride 2 across empty space
            nx0 = max(x0 - 2, 0); nx1 = min(x1 + 2, NB - 1);
            ny0 = max(y0 - 2, 0); ny1 = min(y1 + 2, NB - 1);
        }

        // process delta region, one lane per row (rect-height independent)
        for (int yy = ny0 + lane; yy <= ny1; yy += 32) {
            int r = yy * NB;
            if (yy < y0 || yy > y1) {
                int bg = s_ofs[r + nx0], en = s_ofs[r + nx1 + 1];
                for (int p = bg; p < en; ++p) PROC1(p);
            } else {
                if (nx0 < x0) {
                    int bg = s_ofs[r + nx0], en = s_ofs[r + x0];
                    for (int p = bg; p < en; ++p) PROC1(p);
                }
                if (nx1 > x1) {
                    int bg = s_ofs[r + x1 + 1], en = s_ofs[r + nx1 + 1];
                    for (int p = bg; p < en; ++p) PROC1(p);
                }
            }
        }
        x0 = nx0; x1 = nx1; y0 = ny0; y1 = ny1;
    }

    // final exact top-4 via 4 REDUX pop rounds (replaces butterfly merge).
    // Lane lists are sorted + disjoint (unique idx), so each round pops
    // exactly one point; results replicated in all lanes.
    int nn0, nn1, nn2, nn3;
    #define POP_ROUND(NN)                                                  \
        do {                                                               \
            unsigned um = __reduce_min_sync(FULLMASK, __float_as_uint(s0));\
            int cand = (__float_as_uint(s0) == um) ? i0 : 0x7FFFFFFF;      \
            int im = __reduce_min_sync(FULLMASK, cand);                    \
            if (__float_as_uint(s0) == um && i0 == im) {                   \
                s0 = s1; i0 = i1; s1 = s2; i1 = i2;                        \
                s2 = s3; i2 = i3; s3 = INF; i3 = n;                        \
            }                                                              \
            NN = im;                                                       \
        } while (0)
    POP_ROUND(nn0);
    POP_ROUND(nn1);
    POP_ROUND(nn2);
    POP_ROUND(nn3);

    // epilogue: lane = k*8 + e computes out[i][k*8 + e]
    const int k = lane >> 3;
    const int e = lane & 7;
    int nj = (k == 0) ? nn0 : (k == 1) ? nn1 : (k == 2) ? nn2 : nn3;
    if (nj >= n) nj = (i == 0) ? 1 : 0;   // degenerate-n safety

    float2 pj  = obs2[nj];
    float2 o1j = obs1[nj];

    float rpx = pj.x - qx;
    float rpy = pj.y - qy;
    float rvx = (pj.x - o1j.x) - (qx - o1i.x);
    float rvy = (pj.y - o1j.y) - (qy - o1i.y);

    float acc = bias[e];
    acc = fmaf(rpx, W[0 * 8 + e], acc);
    acc = fmaf(rpy, W[1 * 8 + e], acc);
    acc = fmaf(rvx, W[2 * 8 + e], acc);
    acc = fmaf(rvy, W[3 * 8 + e], acc);

    out[i * 32 + lane] = fmaxf(acc, 0.0f);
}

extern "C" void kernel_launch(void* const* d_in, const int* in_sizes, int n_in,
                              void* d_out, int out_size) {
    const float2* obs1 = (const float2*)d_in[0];  // [N, 2]
    const float2* obs2 = (const float2*)d_in[1];  // [N, 2]
    const float*  W    = (const float*)d_in[2];   // [4, 8]
    const float*  b    = (const float*)d_in[3];   // [8]
    float* out = (float*)d_out;                    // [N, 32]

    int n = in_sizes[0] / 2;
    if (n > NTRK) n = NTRK;

    static bool attr_set = false;
    if (!attr_set) {
        cudaFuncSetAttribute(nn_pool_fused,
                             cudaFuncAttributeMaxDynamicSharedMemorySize,
                             SM_TOTAL);
        attr_set = true;
    }

    int blocks = (n + TRACKS_PER_BLOCK - 1) / TRACKS_PER_BLOCK;  // 147 <= 148
    nn_pool_fused<<<blocks, THREADS, SM_TOTAL>>>(obs1, obs2, W, b, out, n);
}

// round 17
// speedup vs baseline: 1.6645x; 1.0021x over previous
#include <cuda_runtime.h>
#include <math_constants.h>

#define NTRK 4096
#define NB 64
#define NBINS (NB * NB)
#define FULLMASK 0xffffffffu
#define THREADS 1024
#define TRACKS_PER_BLOCK 28          // 147 blocks -> all 148 SMs busy

// fixed bbox (exact for any input via clamping; bound argument below)
#define BB_MIN (-6.0f)
#define BB_W   (12.0f)
#define CW     (BB_W / (float)NB)    // 0.1875, exact in fp32
#define INVW   ((float)NB / BB_W)
#define EPSB   0.0005f               // fp safety margin

// smem layout
#define SM_PTS_OFF  0                // float4[4096] = 65536
#define SM_OFS_OFF  65536            // int[4097]    = 16388
#define SM_WSUM_OFF (65536 + 16400)  // int[32]      = 128
#define SM_TOTAL    (65536 + 16400 + 128)

#define INF CUDART_INF_F

// lexicographic (d2, idx) insert into a sorted-4 list; exact top_k tie-break.
// Order-independent, so any scan order is exact.
__device__ __forceinline__ void lex_insert(float dv, int jv,
    float& s0, float& s1, float& s2, float& s3,
    int& i0, int& i1, int& i2, int& i3)
{
    if ((dv < s3) || (dv == s3 && jv < i3)) {
        if ((dv < s1) || (dv == s1 && jv < i1)) {
            s3 = s2; i3 = i2; s2 = s1; i2 = i1;
            if ((dv < s0) || (dv == s0 && jv < i0)) { s1 = s0; i1 = i0; s0 = dv; i0 = jv; }
            else                                    { s1 = dv; i1 = jv; }
        } else {
            if ((dv < s2) || (dv == s2 && jv < i2)) { s3 = s2; i3 = i2; s2 = dv; i2 = jv; }
            else                                    { s3 = dv; i3 = jv; }
        }
    }
}

__global__ __launch_bounds__(THREADS)
void nn_pool_fused(const float2* __restrict__ obs1,
                   const float2* __restrict__ obs2,
                   const float* __restrict__ W,
                   const float* __restrict__ bias,
                   float* __restrict__ out,
                   int n)
{
    extern __shared__ char smem_raw[];
    float4* s_pts  = (float4*)(smem_raw + SM_PTS_OFF);
    int*    s_ofs  = (int*)   (smem_raw + SM_OFS_OFF);   // [NBINS+1]
    int*    s_wsum = (int*)   (smem_raw + SM_WSUM_OFF);

    const int t    = threadIdx.x;
    const int lane = t & 31;
    const int warp = t >> 5;

    // ---------------- per-block grid build (all in SMEM, R11-proven) -------
    for (int c = t; c < NBINS + 1; c += THREADS) s_ofs[c] = 0;
    __syncthreads();

    float px[4], py[4];
    int   bins[4], rank[4];
    #pragma unroll
    for (int k = 0; k < 4; ++k) {
        int p = t + k * THREADS;
        bins[k] = -1;
        if (p < n) {
            float2 v = obs2[p];
            px[k] = v.x; py[k] = v.y;
            int bx = min(NB - 1, max(0, (int)((v.x - BB_MIN) * INVW)));
            int by = min(NB - 1, max(0, (int)((v.y - BB_MIN) * INVW)));
            bins[k] = by * NB + bx;
            rank[k] = atomicAdd(&s_ofs[bins[k]], 1);  // return value = rank
        }
    }
    __syncthreads();

    int c4[4];
    #pragma unroll
    for (int k = 0; k < 4; ++k) c4[k] = s_ofs[4 * t + k];
    int tot = c4[0] + c4[1] + c4[2] + c4[3];
    int incl = tot;
    #pragma unroll
    for (int off = 1; off < 32; off <<= 1) {
        int v = __shfl_up_sync(FULLMASK, incl, off);
        if (lane >= off) incl += v;
    }
    if (lane == 31) s_wsum[warp] = incl;
    __syncthreads();
    if (warp == 0) {
        int v = s_wsum[lane];
        int wi = v;
        #pragma unroll
        for (int off = 1; off < 32; off <<= 1) {
            int u = __shfl_up_sync(FULLMASK, wi, off);
            if (lane >= off) wi += u;
        }
        s_wsum[lane] = wi - v;
    }
    __syncthreads();
    int run = s_wsum[warp] + (incl - tot);
    #pragma unroll
    for (int k = 0; k < 4; ++k) {
        s_ofs[4 * t + k] = run;
        run += c4[k];
    }
    if (t == THREADS - 1) s_ofs[NBINS] = run;
    __syncthreads();

    #pragma unroll
    for (int k = 0; k < 4; ++k) {
        if (bins[k] >= 0) {
            s_pts[s_ofs[bins[k]] + rank[k]] =
                make_float4(px[k], py[k], __int_as_float(t + k * THREADS), 0.0f);
        }
    }
    __syncthreads();

    // ---------------- search: one warp per track, all SMEM ----------------
    const int i = blockIdx.x * TRACKS_PER_BLOCK + warp;
    if (warp >= TRACKS_PER_BLOCK || i >= n) return;

    const float2 q = obs2[i];
    const float qx = q.x, qy = q.y;
    const float2 o1i = obs1[i];    // prefetch: hides L2 latency behind search

    const int cx = min(NB - 1, max(0, (int)((qx - BB_MIN) * INVW)));
    const int cy = min(NB - 1, max(0, (int)((qy - BB_MIN) * INVW)));

    float s0 = INF, s1 = INF, s2 = INF, s3 = INF;
    int   i0 = n,  i1 = n,  i2 = n,  i3 = n;

    #define PROC1(p_)                                                  \
        do {                                                           \
            float4 pt = s_pts[p_];                                     \
            int pj = __float_as_int(pt.z);                             \
            float dx = pt.x - qx, dy = pt.y - qy;                      \
            float dd = fmaf(dx, dx, dy * dy);                          \
            if (pj != i) lex_insert(dd, pj, s0, s1, s2, s3, i0, i1, i2, i3); \
        } while (0)

    #define SPAN_SCAN(bg_, en_)                                        \
        for (int p = (bg_) + lane; p < (en_); p += 32) PROC1(p);

    // initial 3x3 rect: each row is a contiguous span, scanned lane-striped
    int x0 = max(cx - 1, 0), x1 = min(cx + 1, NB - 1);
    int y0 = max(cy - 1, 0), y1 = min(cy + 1, NB - 1);
    for (int y = y0; y <= y1; ++y) {
        int r = y * NB;
        int bg = s_ofs[r + x0], en = s_ofs[r + x1 + 1];
        SPAN_SCAN(bg, en);
    }

    while (true) {
        // lower bound on distance to any unprocessed point. Grid-edge sides
        // contribute +inf: all points (incl. clamped outliers) live in bins
        // 0..NB-1, and a clamped outlier lies farther out than its bin's
        // nominal region, so interior-side bounds remain valid lower bounds.
        float bl = (x0 > 0)      ? (qx - (BB_MIN + (float)x0 * CW))       : INF;
        float br = (x1 < NB - 1) ? ((BB_MIN + (float)(x1 + 1) * CW) - qx) : INF;
        float bd = (y0 > 0)      ? (qy - (BB_MIN + (float)y0 * CW))       : INF;
        float bu = (y1 < NB - 1) ? ((BB_MIN + (float)(y1 + 1) * CW) - qy) : INF;
        float bmin = fminf(fminf(bl, br), fminf(bd, bu));

        if (isinf(bmin)) break;   // rect covers entire grid

        float be = fmaxf(bmin - EPSB, 0.0f);
        float b2 = be * be;
        // exact termination: lane lists hold DISJOINT candidates, so
        // sum(cnt) >= 4 <=> >=4 distinct points strictly nearer than any
        // unprocessed point.
        int cnt = (s3 <= b2) ? 4 : (s2 <= b2) ? 3 : (s1 <= b2) ? 2 : (s0 <= b2) ? 1 : 0;
        if (__reduce_add_sync(FULLMASK, cnt) >= 4) break;

        // U = min over lanes of s3 (positive floats / +inf are int-ordered):
        // valid upper bound on global 4th-best d2 once any lane holds 4.
        float U = __uint_as_float(__reduce_min_sync(FULLMASK, __float_as_uint(s3)));

        if (isinf(U)) {
            // No single lane holds 4, but the WARP may: exact global 4th-best
            // via 4 REDUX pop rounds on copies (lane lists stay intact).
            // Rare path (sparse tracks only), executed at most ~once per track.
            int myc = (s0 < INF) + (s1 < INF) + (s2 < INF) + (s3 < INF);
            if (__reduce_add_sync(FULLMASK, myc) >= 4) {
                float p0 = s0, p1 = s1, p2 = s2, p3 = s3;
                int   e0 = i0, e1 = i1, e2 = i2, e3 = i3;
                #pragma unroll
                for (int rnd = 0; rnd < 4; ++rnd) {
                    unsigned um = __reduce_min_sync(FULLMASK, __float_as_uint(p0));
                    int cand = (__float_as_uint(p0) == um) ? e0 : 0x7FFFFFFF;
                    int im = __reduce_min_sync(FULLMASK, cand);
                    if (__float_as_uint(p0) == um && e0 == im) {
                        p0 = p1; e0 = e1; p1 = p2; e1 = e2;
                        p2 = p3; e2 = e3; p3 = INF; e3 = n;
                    }
                    U = __uint_as_float(um);   // after 4 rounds = exact 4th-best
                }
            }
        }

        int nx0, nx1, ny0, ny1;
        if (U < INF) {
            // jump: final answer lies within radius sqrt(U)+eps of q
            float ru = sqrtf(U) + EPSB;
            nx0 = min(x0, max(0,      (int)((qx - ru - BB_MIN) * INVW)));
            nx1 = max(x1, min(NB - 1, (int)((qx + ru - BB_MIN) * INVW)));
            ny0 = min(y0, max(0,      (int)((qy - ru - BB_MIN) * INVW)));
            ny1 = max(y1, min(NB - 1, (int)((qy + ru - BB_MIN) * INVW)));
            if (nx0 == x0 && nx1 == x1 && ny0 == y0 && ny1 == y1) {
                // fp edge: force progress
                nx0 = max(x0 - 1, 0); nx1 = min(x1 + 1, NB - 1);
                ny0 = max(y0 - 1, 0); ny1 = min(y1 + 1, NB - 1);
            }
        } else {
            // warp holds <4 candidates total: stride 2 across sparse space
            nx0 = max(x0 - 2, 0); nx1 = min(x1 + 2, NB - 1);
            ny0 = max(y0 - 2, 0); ny1 = min(y1 + 2, NB - 1);
        }

        // process delta region, one lane per row (rect-height independent)
        for (int yy = ny0 + lane; yy <= ny1; yy += 32) {
            int r = yy * NB;
            if (yy < y0 || yy > y1) {
                int bg = s_ofs[r + nx0], en = s_ofs[r + nx1 + 1];
                for (int p = bg; p < en; ++p) PROC1(p);
            } else {
                if (nx0 < x0) {
                    int bg = s_ofs[r + nx0], en = s_ofs[r + x0];
                    for (int p = bg; p < en; ++p) PROC1(p);
                }
                if (nx1 > x1) {
                    int bg = s_ofs[r + x1 + 1], en = s_ofs[r + nx1 + 1];
                    for (int p = bg; p < en; ++p) PROC1(p);
                }
            }
        }
        x0 = nx0; x1 = nx1; y0 = ny0; y1 = ny1;
    }

    // final exact top-4 via 4 REDUX pop rounds (lane lists sorted + disjoint,
    // unique idx -> each round pops exactly one point; replicated in all lanes)
    int nn0, nn1, nn2, nn3;
    #define POP_ROUND(NN)                                                  \
        do {                                                               \
            unsigned um = __reduce_min_sync(FULLMASK, __float_as_uint(s0));\
            int cand = (__float_as_uint(s0) == um) ? i0 : 0x7FFFFFFF;      \
            int im = __reduce_min_sync(FULLMASK, cand);                    \
            if (__float_as_uint(s0) == um && i0 == im) {                   \
                s0 = s1; i0 = i1; s1 = s2; i1 = i2;                        \
                s2 = s3; i2 = i3; s3 = INF; i3 = n;                        \
            }                                                              \
            NN = im;                                                       \
        } while (0)
    POP_ROUND(nn0);
    POP_ROUND(nn1);
    POP_ROUND(nn2);
    POP_ROUND(nn3);

    // epilogue: lane = k*8 + e computes out[i][k*8 + e]
    const int k = lane >> 3;
    const int e = lane & 7;
    int nj = (k == 0) ? nn0 : (k == 1) ? nn1 : (k == 2) ? nn2 : nn3;
    if (nj >= n) nj = (i == 0) ? 1 : 0;   // degenerate-n safety

    float2 pj  = obs2[nj];
    float2 o1j = obs1[nj];

    float rpx = pj.x - qx;
    float rpy = pj.y - qy;
    float rvx = (pj.x - o1j.x) - (qx - o1i.x);
    float rvy = (pj.y - o1j.y) - (qy - o1i.y);

    float acc = bias[e];
    acc = fmaf(rpx, W[0 * 8 + e], acc);
    acc = fmaf(rpy, W[1 * 8 + e], acc);
    acc = fmaf(rvx, W[2 * 8 + e], acc);
    acc = fmaf(rvy, W[3 * 8 + e], acc);

    out[i * 32 + lane] = fmaxf(acc, 0.0f);
}

extern "C" void kernel_launch(void* const* d_in, const int* in_sizes, int n_in,
                              void* d_out, int out_size) {
    const float2* obs1 = (const float2*)d_in[0];  // [N, 2]
    const float2* obs2 = (const float2*)d_in[1];  // [N, 2]
    const float*  W    = (const float*)d_in[2];   // [4, 8]
    const float*  b    = (const float*)d_in[3];   // [8]
    float* out = (float*)d_out;                    // [N, 32]

    int n = in_sizes[0] / 2;
    if (n > NTRK) n = NTRK;

    static bool attr_set = false;
    if (!attr_set) {
        cudaFuncSetAttribute(nn_pool_fused,
                             cudaFuncAttributeMaxDynamicSharedMemorySize,
                             SM_TOTAL);
        attr_set = true;
    }

    int blocks = (n + TRACKS_PER_BLOCK - 1) / TRACKS_PER_BLOCK;  // 147 <= 148
    nn_pool_fused<<<blocks, THREADS, SM_TOTAL>>>(obs1, obs2, W, b, out, n);
}